// round 6
// baseline (speedup 1.0000x reference)
#include <cuda_runtime.h>
#include <math.h>

// log(entmax_bisect_1.5(X)) row-wise. X: (rows, 32000) fp32, out same shape.
//
// p(z) = relu(z)^2 with z = 0.5*X - tau, tau s.t. sum p = 1. Dense support
// gives closed-form tau from S1, S2 (validated by tau <= min(z)); fallback
// is the exact 50-iter reference bisection over the L2-resident row.
//
// Pipelined persistent kernel, 3 CTAs/SM x 512 threads:
//   each iteration fuses [DRAM-read stats pass of the NEXT row] with
//   [L2 re-read + output store of the CURRENT row], so DRAM sees a steady
//   read/write mix instead of alternating unidirectional bursts.
// Fixes vs the failed R5 attempt:
//   - __stwt output stores (write-through): no dirty-line L2 occupancy,
//     so the 57MB read working set stays resident (R5 evicted it).
//   - dynamic row tickets via atomic counter: no static-stride tail.

constexpr int D    = 32000;
constexpr int D4   = D / 4;
constexpr int NT   = 512;
constexpr int NW   = NT / 32;
constexpr int GRID = 148 * 3;   // 3 CTAs/SM

__device__ int g_row_ctr;

__global__ void init_ctr_kernel(int v) { g_row_ctr = v; }

__device__ __forceinline__ float wsum(float v) {
#pragma unroll
    for (int o = 16; o; o >>= 1) v += __shfl_xor_sync(0xffffffffu, v, o);
    return v;
}
__device__ __forceinline__ float wmin(float v) {
#pragma unroll
    for (int o = 16; o; o >>= 1) v = fminf(v, __shfl_xor_sync(0xffffffffu, v, o));
    return v;
}
__device__ __forceinline__ float wmax(float v) {
#pragma unroll
    for (int o = 16; o; o >>= 1) v = fmaxf(v, __shfl_xor_sync(0xffffffffu, v, o));
    return v;
}

struct SRed {
    float A[NW], B[NW], C[NW];
    float tau, logsum, flag, bc;
    int   next;
};

// Block-wide sum of relu(0.5*x[i] - tau)^2 over a row, broadcast.
// Fallback path only — row is L2-resident.
__device__ float block_relu2_sum(const float4* __restrict__ x4, float tau, SRed* sh) {
    float acc = 0.f;
    for (int i = threadIdx.x; i < D4; i += NT) {
        float4 v = x4[i];
        float t;
        t = fmaxf(fmaf(0.5f, v.x, -tau), 0.f); acc = fmaf(t, t, acc);
        t = fmaxf(fmaf(0.5f, v.y, -tau), 0.f); acc = fmaf(t, t, acc);
        t = fmaxf(fmaf(0.5f, v.z, -tau), 0.f); acc = fmaf(t, t, acc);
        t = fmaxf(fmaf(0.5f, v.w, -tau), 0.f); acc = fmaf(t, t, acc);
    }
    acc = wsum(acc);
    int wid = threadIdx.x >> 5, lid = threadIdx.x & 31;
    __syncthreads();
    if (lid == 0) sh->A[wid] = acc;
    __syncthreads();
    if (threadIdx.x == 0) {
        float s = 0.f;
#pragma unroll
        for (int w = 0; w < NW; ++w) s += sh->A[w];
        sh->bc = s;
    }
    __syncthreads();
    return sh->bc;
}

// Reduce raw per-thread stats of a row, publish tau/logsum to shared.
__device__ void compute_tau(float s1, float s2, float mn,
                            const float4* __restrict__ xr, SRed* sh) {
    const int tid = threadIdx.x;
    const int wid = tid >> 5, lid = tid & 31;
    s1 = wsum(s1); s2 = wsum(s2); mn = wmin(mn);
    if (lid == 0) { sh->A[wid] = s1; sh->B[wid] = s2; sh->C[wid] = mn; }
    __syncthreads();

    if (tid == 0) {
        float S1 = 0.f, S2 = 0.f, MN = INFINITY;
#pragma unroll
        for (int w = 0; w < NW; ++w) {
            S1 += sh->A[w]; S2 += sh->B[w]; MN = fminf(MN, sh->C[w]);
        }
        S1 *= 0.5f;            // raw sums -> z = 0.5*x domain
        S2 *= 0.25f;
        MN *= 0.5f;
        const float k = (float)D;
        float disc  = fmaxf(fmaf(S1, S1, -k * (S2 - 1.0f)), 0.f);
        float tau   = (S1 - sqrtf(disc)) / k;
        float sum_p = fmaf(k * tau, tau, fmaf(-2.f * S1, tau, S2));
        sh->tau = tau;
        if (tau <= MN && sum_p > 0.f) {           // dense support
            sh->logsum = __logf(sum_p);
            sh->flag = 1.f;
        } else {
            sh->flag = 0.f;
        }
    }
    __syncthreads();

    // Fallback: exact reference bisection (block-uniform branch).
    if (sh->flag == 0.f) {
        float mx = -INFINITY;
        for (int i = tid; i < D4; i += NT) {
            float4 v = xr[i];
            mx = fmaxf(mx, fmaxf(fmaxf(v.x, v.y), fmaxf(v.z, v.w)));
        }
        mx = wmax(mx);
        __syncthreads();
        if (lid == 0) sh->A[wid] = mx;
        __syncthreads();
        if (tid == 0) {
            float M = -INFINITY;
#pragma unroll
            for (int w = 0; w < NW; ++w) M = fmaxf(M, sh->A[w]);
            sh->bc = 0.5f * M;
        }
        __syncthreads();
        float mxv    = sh->bc;
        float tau_lo = mxv - 1.0f;
        float tau_hi = mxv - sqrtf(1.0f / (float)D);
        float f_lo   = block_relu2_sum(xr, tau_lo, sh) - 1.0f;
        float dm     = tau_hi - tau_lo;
        float tau_m  = tau_lo;
        for (int it = 0; it < 50; ++it) {
            dm *= 0.5f;
            tau_m = tau_lo + dm;
            float f_m = block_relu2_sum(xr, tau_m, sh) - 1.0f;
            if (f_m * f_lo >= 0.f) tau_lo = tau_m;  // uniform across block
        }
        float sp = block_relu2_sum(xr, tau_m, sh);
        if (tid == 0) {
            sh->tau = tau_m;
            sh->logsum = __logf(sp);
        }
        __syncthreads();
    }
}

__device__ __forceinline__ float4 log_p4(float4 v, float tau, float logsum) {
    float4 r; float t;
    t = fmaf(0.5f, v.x, -tau); r.x = (t > 0.f) ? fmaf(2.f, __logf(t), -logsum) : -INFINITY;
    t = fmaf(0.5f, v.y, -tau); r.y = (t > 0.f) ? fmaf(2.f, __logf(t), -logsum) : -INFINITY;
    t = fmaf(0.5f, v.z, -tau); r.z = (t > 0.f) ? fmaf(2.f, __logf(t), -logsum) : -INFINITY;
    t = fmaf(0.5f, v.w, -tau); r.w = (t > 0.f) ? fmaf(2.f, __logf(t), -logsum) : -INFINITY;
    return r;
}

__global__ void __launch_bounds__(NT, 3)
log_entmax_kernel(const float* __restrict__ X, float* __restrict__ Y, int rows) {
    __shared__ SRed sh;
    const int tid = threadIdx.x;
    int r = blockIdx.x;
    if (r >= rows) return;

    const float4* __restrict__ X4 = reinterpret_cast<const float4*>(X);
    float4* __restrict__ Y4       = reinterpret_cast<float4*>(Y);

    // ---- Prologue: stats pass for this CTA's first row (fills L2) ----
    {
        const float4* xr = X4 + (size_t)r * D4;
        float s1 = 0.f, s2 = 0.f, mn = INFINITY;
#pragma unroll 2
        for (int i = tid; i < D4; i += NT) {
            float4 v = xr[i];
            s1 += (v.x + v.y) + (v.z + v.w);
            s2 = fmaf(v.x, v.x, s2); s2 = fmaf(v.y, v.y, s2);
            s2 = fmaf(v.z, v.z, s2); s2 = fmaf(v.w, v.w, s2);
            mn = fminf(mn, fminf(fminf(v.x, v.y), fminf(v.z, v.w)));
        }
        compute_tau(s1, s2, mn, xr, &sh);
    }

    // ---- Pipelined row loop (dynamic row tickets) ----
    for (;;) {
        if (tid == 0) sh.next = atomicAdd(&g_row_ctr, 1);
        __syncthreads();
        const int rn = sh.next;
        const float4* __restrict__ xc = X4 + (size_t)r * D4;
        float4* __restrict__ yc       = Y4 + (size_t)r * D4;
        const float tau    = sh.tau;
        const float logsum = sh.logsum;
        __syncthreads();   // everyone has tau/logsum before sh is reused

        if (rn < rows) {
            // Fused: DRAM-read stats of row rn + L2-reread/write-through of row r.
            const float4* __restrict__ xn = X4 + (size_t)rn * D4;
            float s1 = 0.f, s2 = 0.f, mn = INFINITY;
#pragma unroll 2
            for (int i = tid; i < D4; i += NT) {
                float4 v = xn[i];                 // DRAM read (fills L2)
                s1 += (v.x + v.y) + (v.z + v.w);
                s2 = fmaf(v.x, v.x, s2); s2 = fmaf(v.y, v.y, s2);
                s2 = fmaf(v.z, v.z, s2); s2 = fmaf(v.w, v.w, s2);
                mn = fminf(mn, fminf(fminf(v.x, v.y), fminf(v.z, v.w)));
                float4 c = __ldcs(&xc[i]);        // L2 hit, evict-first
                __stwt(&yc[i], log_p4(c, tau, logsum));  // write-through
            }
            compute_tau(s1, s2, mn, xn, &sh);     // contains __syncthreads
            r = rn;
        } else {
            // Epilogue: output pass for the final row.
#pragma unroll 2
            for (int i = tid; i < D4; i += NT) {
                float4 c = __ldcs(&xc[i]);
                __stwt(&yc[i], log_p4(c, tau, logsum));
            }
            return;
        }
    }
}

extern "C" void kernel_launch(void* const* d_in, const int* in_sizes, int n_in,
                              void* d_out, int out_size) {
    const float* X = (const float*)d_in[0];
    float* Y = (float*)d_out;
    const int rows = in_sizes[0] / D;
    const int grid = rows < GRID ? rows : GRID;
    init_ctr_kernel<<<1, 1>>>(grid);          // rows [0,grid) are prologue-owned
    log_entmax_kernel<<<grid, NT>>>(X, Y, rows);
}

// round 7
// speedup vs baseline: 1.5215x; 1.5215x over previous
#include <cuda_runtime.h>
#include <math.h>

// log(entmax_bisect_1.5(X)) row-wise. X: (rows, 32000) fp32, out same shape.
//
// p(z) = relu(z)^2, z = 0.5*X - tau, tau s.t. sum p = 1. Dense support gives
// closed-form tau from S1, S2 (validated tau <= min(z)); fallback = exact
// 50-iter reference bisection over the L2-resident row.
//
// R4 structure (best known: 3 CTAs/SM x 512, pass1 DRAM-read stats, pass2
// L2 re-read + streaming store; 55MB L2 set). New in R7: pass 2 is
// MUFU-bound (1 lg2/elem ~= 110us chip-wide), so 1 of each 4 lanes computes
// log via an FMA-pipe polynomial (exponent split + deg-5 log1p, |err|<6e-4
// absolute on out ~ -10), balancing MUFU (~82us) and FMA (~89us).

constexpr int D  = 32000;
constexpr int D4 = D / 4;
constexpr int NT = 512;
constexpr int NW = NT / 32;

constexpr float TWO_LN2 = 1.3862943611198906f;   // 2*ln(2)

__device__ __forceinline__ float wsum(float v) {
#pragma unroll
    for (int o = 16; o; o >>= 1) v += __shfl_xor_sync(0xffffffffu, v, o);
    return v;
}
__device__ __forceinline__ float wmin(float v) {
#pragma unroll
    for (int o = 16; o; o >>= 1) v = fminf(v, __shfl_xor_sync(0xffffffffu, v, o));
    return v;
}
__device__ __forceinline__ float wmax(float v) {
#pragma unroll
    for (int o = 16; o; o >>= 1) v = fmaxf(v, __shfl_xor_sync(0xffffffffu, v, o));
    return v;
}

// MUFU path: out = 2*log(t) - logsum = log2(t)*2ln2 - logsum
__device__ __forceinline__ float logp_mufu(float t, float logsum) {
    return (t > 0.f) ? fmaf(__log2f(t), TWO_LN2, -logsum) : -INFINITY;
}

// FMA-pipe path: exponent/mantissa split, deg-5 log1p Taylor (x2 folded).
// t = m * 2^e with m in [2/3, 4/3); out = e*2ln2 + 2*log1p(m-1) - logsum.
__device__ __forceinline__ float logp_poly(float t, float logsum) {
    int   i = __float_as_int(t);
    int   k = (i - 0x3f2aaaab) & 0xff800000;
    float m = __int_as_float(i - k);
    float e = (float)(k >> 23);
    float u = m - 1.0f;                          // |u| <= 1/3
    float h;                                     // 2*log1p(u) Horner
    h = fmaf(0.4f,         u, -0.5f);
    h = fmaf(h,            u,  0.66666667f);
    h = fmaf(h,            u, -1.0f);
    h = fmaf(h,            u,  2.0f);
    float g = fmaf(h, u, -logsum);
    float r = fmaf(e, TWO_LN2, g);
    return (t > 0.f) ? r : -INFINITY;
}

// Block-wide sum of relu(0.5*x[i] - tau)^2 over the row, broadcast.
// Fallback path only — row is L2-resident.
__device__ float block_relu2_sum(const float4* __restrict__ x4, float tau,
                                 float* redbuf, float* bc) {
    float acc = 0.f;
    for (int i = threadIdx.x; i < D4; i += NT) {
        float4 v = x4[i];
        float t;
        t = fmaxf(fmaf(0.5f, v.x, -tau), 0.f); acc = fmaf(t, t, acc);
        t = fmaxf(fmaf(0.5f, v.y, -tau), 0.f); acc = fmaf(t, t, acc);
        t = fmaxf(fmaf(0.5f, v.z, -tau), 0.f); acc = fmaf(t, t, acc);
        t = fmaxf(fmaf(0.5f, v.w, -tau), 0.f); acc = fmaf(t, t, acc);
    }
    acc = wsum(acc);
    int wid = threadIdx.x >> 5, lid = threadIdx.x & 31;
    __syncthreads();
    if (lid == 0) redbuf[wid] = acc;
    __syncthreads();
    if (threadIdx.x == 0) {
        float s = 0.f;
#pragma unroll
        for (int w = 0; w < NW; ++w) s += redbuf[w];
        *bc = s;
    }
    __syncthreads();
    return *bc;
}

__global__ void __launch_bounds__(NT, 3)
log_entmax_kernel(const float* __restrict__ X, float* __restrict__ Y) {
    __shared__ float redA[NW], redB[NW], redC[NW];
    __shared__ float s_tau, s_logsum, s_flag, s_bc;

    const int tid = threadIdx.x;
    const int wid = tid >> 5, lid = tid & 31;
    const float4* __restrict__ x4 = reinterpret_cast<const float4*>(X) + (size_t)blockIdx.x * D4;
    float4* __restrict__ y4       = reinterpret_cast<float4*>(Y)       + (size_t)blockIdx.x * D4;

    // ---- Pass 1: stream row from DRAM (fills L2), raw sums (no scaling) ----
    float s1 = 0.f, s2 = 0.f, mn = INFINITY;
#pragma unroll 4
    for (int i = tid; i < D4; i += NT) {
        float4 v = x4[i];
        s1 += (v.x + v.y) + (v.z + v.w);
        s2 = fmaf(v.x, v.x, s2); s2 = fmaf(v.y, v.y, s2);
        s2 = fmaf(v.z, v.z, s2); s2 = fmaf(v.w, v.w, s2);
        mn = fminf(mn, fminf(fminf(v.x, v.y), fminf(v.z, v.w)));
    }
    s1 = wsum(s1); s2 = wsum(s2); mn = wmin(mn);
    if (lid == 0) { redA[wid] = s1; redB[wid] = s2; redC[wid] = mn; }
    __syncthreads();

    if (tid == 0) {
        float S1 = 0.f, S2 = 0.f, MN = INFINITY;
#pragma unroll
        for (int w = 0; w < NW; ++w) {
            S1 += redA[w]; S2 += redB[w]; MN = fminf(MN, redC[w]);
        }
        S1 *= 0.5f;            // raw sums -> z = 0.5*x domain
        S2 *= 0.25f;
        MN *= 0.5f;
        const float k = (float)D;
        float disc  = fmaxf(fmaf(S1, S1, -k * (S2 - 1.0f)), 0.f);
        float tau   = (S1 - sqrtf(disc)) / k;
        float sum_p = fmaf(k * tau, tau, fmaf(-2.f * S1, tau, S2));
        s_tau = tau;
        if (tau <= MN && sum_p > 0.f) {           // dense support: closed form valid
            s_logsum = __logf(sum_p);
            s_flag = 1.f;
        } else {
            s_flag = 0.f;
        }
    }
    __syncthreads();

    // ---- Fallback: exact reference bisection (block-uniform branch) ----
    if (s_flag == 0.f) {
        float mx = -INFINITY;
        for (int i = tid; i < D4; i += NT) {
            float4 v = x4[i];
            mx = fmaxf(mx, fmaxf(fmaxf(v.x, v.y), fmaxf(v.z, v.w)));
        }
        mx = wmax(mx);
        __syncthreads();
        if (lid == 0) redA[wid] = mx;
        __syncthreads();
        if (tid == 0) {
            float M = -INFINITY;
#pragma unroll
            for (int w = 0; w < NW; ++w) M = fmaxf(M, redA[w]);
            s_bc = 0.5f * M;
        }
        __syncthreads();
        float mxv    = s_bc;
        float tau_lo = mxv - 1.0f;
        float tau_hi = mxv - sqrtf(1.0f / (float)D);
        float f_lo   = block_relu2_sum(x4, tau_lo, redA, &s_bc) - 1.0f;
        float dm     = tau_hi - tau_lo;
        float tau_m  = tau_lo;
        for (int it = 0; it < 50; ++it) {
            dm *= 0.5f;
            tau_m = tau_lo + dm;
            float f_m = block_relu2_sum(x4, tau_m, redA, &s_bc) - 1.0f;
            if (f_m * f_lo >= 0.f) tau_lo = tau_m;  // uniform across block
        }
        float sp = block_relu2_sum(x4, tau_m, redA, &s_bc);
        if (tid == 0) {
            s_tau = tau_m;
            s_logsum = __logf(sp);
        }
        __syncthreads();
    }

    const float tau    = s_tau;
    const float logsum = s_logsum;

    // ---- Pass 2: re-read X (L2 hit), hybrid MUFU/poly log, stream out ----
#pragma unroll 4
    for (int i = tid; i < D4; i += NT) {
        float4 v = __ldcs(&x4[i]);   // evict-first: row is dead after this read
        float4 r;
        r.x = logp_mufu(fmaf(0.5f, v.x, -tau), logsum);
        r.y = logp_mufu(fmaf(0.5f, v.y, -tau), logsum);
        r.z = logp_mufu(fmaf(0.5f, v.z, -tau), logsum);
        r.w = logp_poly(fmaf(0.5f, v.w, -tau), logsum);  // FMA-pipe offload
        __stcs(&y4[i], r);           // streaming store: don't pollute L2
    }
}

extern "C" void kernel_launch(void* const* d_in, const int* in_sizes, int n_in,
                              void* d_out, int out_size) {
    const float* X = (const float*)d_in[0];
    float* Y = (float*)d_out;
    const int rows = in_sizes[0] / D;
    log_entmax_kernel<<<rows, NT>>>(X, Y);
}